// round 7
// baseline (speedup 1.0000x reference)
#include <cuda_runtime.h>
#include <math.h>

#define BB   256
#define LSEQ 1800
#define FF   50
#define EE   4
#define HH   32
#define DD   64
#define G3   96      // 3*H
#define HU   32
#define NP   (2 * BB)        // 512 routed pairs
#define LT   90              // L-steps per GEMM block (1800/90 = 20 chunks)

typedef unsigned long long ull;

// ---------------- device scratch (no runtime allocation allowed) ----------
__device__ float g_Wc[EE * G3 * FF];           // Wih0 @ W_in (per expert 96x50)
__device__ int   g_pair_e[NP];                  // routed expert per pair
__device__ float g_pair_w[NP];                  // softmax weight per pair
__device__ float g_pred[NP];                    // expert prediction per pair
__device__ float g_c0[NP * G3];                 // fused layer-0 input bias
__device__ float g_xg[(size_t)NP * LSEQ * G3];  // precomputed input gates

// ---------------- packed f32x2 helpers ------------------------------------
__device__ __forceinline__ ull pk(float lo, float hi) {
    ull r; asm("mov.b64 %0, {%1, %2};" : "=l"(r) : "f"(lo), "f"(hi)); return r;
}
__device__ __forceinline__ float2 upk(ull v) {
    float2 r; asm("mov.b64 {%0, %1}, %2;" : "=f"(r.x), "=f"(r.y) : "l"(v)); return r;
}
__device__ __forceinline__ void fma2(ull& d, ull a, ull b) {
    asm("fma.rn.f32x2 %0, %1, %2, %3;" : "=l"(d) : "l"(a), "l"(b), "l"(d));
}

__device__ __forceinline__ float sigm_fast(float x) {
    return __fdividef(1.f, 1.f + __expf(-x));
}
__device__ __forceinline__ float tanh_fast(float x) {
    float e = __expf(2.f * x);
    return 1.f - __fdividef(2.f, e + 1.f);
}

// ---------------- prep: combined input weights Wc = Wih0 @ W_in -----------
__global__ void prep_Wc(const float* __restrict__ Wih0,
                        const float* __restrict__ W_in) {
    int e = blockIdx.x, j = threadIdx.x;
    float wr[DD];
    const float* src = Wih0 + (size_t)(e * G3 + j) * DD;
#pragma unroll
    for (int d = 0; d < DD; ++d) wr[d] = src[d];
    float* dst = g_Wc + (size_t)(e * G3 + j) * FF;
    for (int f = 0; f < FF; ++f) {
        float s = 0.f;
#pragma unroll
        for (int d = 0; d < DD; ++d) s = fmaf(wr[d], __ldg(W_in + d * FF + f), s);
        dst[f] = s;
    }
}

// ---------------- prep: gating (top-2 of 4, softmax over top-2) -----------
__global__ void prep_route(const int* __restrict__ horizon,
                           const float* __restrict__ emb,
                           const float* __restrict__ W_gate,
                           const float* __restrict__ b_gate) {
    int b = threadIdx.x;
    int hb = horizon[b];
    const float* he = emb + (size_t)hb * DD;
    float lg[EE];
#pragma unroll
    for (int e = 0; e < EE; ++e) {
        float s = b_gate[e];
        const float* w = W_gate + e * DD;
#pragma unroll
        for (int d = 0; d < DD; ++d) s = fmaf(w[d], he[d], s);
        lg[e] = s;
    }
    int m1 = 0;
#pragma unroll
    for (int e = 1; e < EE; ++e) if (lg[e] > lg[m1]) m1 = e;
    int m2 = -1;
#pragma unroll
    for (int e = 0; e < EE; ++e) {
        if (e == m1) continue;
        if (m2 < 0 || lg[e] > lg[m2]) m2 = e;
    }
    float e2  = expf(lg[m2] - lg[m1]);
    float inv = 1.f / (1.f + e2);
    g_pair_e[2 * b]     = m1;
    g_pair_e[2 * b + 1] = m2;
    g_pair_w[2 * b]     = inv;
    g_pair_w[2 * b + 1] = e2 * inv;
}

// ---------------- prep: c0(p,j) = bih0 + Wih0_row . (b_in + emb[horizon]) -
__global__ void prep_c0(const int* __restrict__ horizon,
                        const float* __restrict__ b_in,
                        const float* __restrict__ emb,
                        const float* __restrict__ Wih0,
                        const float* __restrict__ bih0) {
    int p = blockIdx.x, j = threadIdx.x;
    int b = p >> 1, e = g_pair_e[p];
    int hb = horizon[b];
    float c0 = bih0[e * G3 + j];
    const float* wi = Wih0 + (size_t)(e * G3 + j) * DD;
    const float* hv = emb + (size_t)hb * DD;
#pragma unroll
    for (int d = 0; d < DD; ++d) c0 = fmaf(wi[d], b_in[d] + hv[d], c0);
    g_c0[p * G3 + j] = c0;
}

// ---------------- xg GEMM: g_xg[p][l][j] = Wc[e][j].x[b][l] + c0(p,j) -----
__global__ void __launch_bounds__(288) xg_gemm(const float* __restrict__ x) {
    __shared__ __align__(16) float sx[LT * FF];

    const int p   = blockIdx.y;
    const int b   = p >> 1;
    const int e   = g_pair_e[p];
    const int t   = threadIdx.x;
    const int j   = t % G3;
    const int sub = t / G3;
    const int l0  = blockIdx.x * LT;

    const float* xsrc = x + (size_t)b * LSEQ * FF + (size_t)l0 * FF;
    for (int i = t; i < LT * FF; i += 288) sx[i] = __ldg(xsrc + i);

    ull wt[FF / 2];
    const ull* wc = (const ull*)(g_Wc + (size_t)(e * G3 + j) * FF);
#pragma unroll
    for (int i = 0; i < FF / 2; ++i) wt[i] = wc[i];
    const float c0 = __ldg(g_c0 + p * G3 + j);

    __syncthreads();

    float* dst = g_xg + ((size_t)p * LSEQ + l0) * G3 + j;
#pragma unroll 1
    for (int l = sub * (LT / 3); l < (sub + 1) * (LT / 3); ++l) {
        const ull* xr = (const ull*)(sx + l * FF);
        ull acc = pk(c0, 0.f);
#pragma unroll
        for (int i = 0; i < FF / 2; ++i) fma2(acc, wt[i], xr[i]);
        float2 u = upk(acc);
        dst[(size_t)l * G3] = u.x + u.y;
    }
}

// ---------------- main: 1-barrier/step fused 2-layer GRU scan -------------
// 512 blocks x 192 threads, occ 4 (single wave).
//   t 0..63    layer-0: j=t>>1, half=t&1; rows {j, j+32, j+64} half-dots
//              (odd lanes also prefetch xg into smem ring, distance 4)
//   t 64..191  layer-1: u=t-64, j=u>>2, q=u&3; rows {j,j+32,j+64} quarter-dots
__global__ void __launch_bounds__(192, 4) moe_gru_scan(
    const float* __restrict__ Whh0, const float* __restrict__ bhh0,
    const float* __restrict__ Wih1, const float* __restrict__ Whh1,
    const float* __restrict__ bih1, const float* __restrict__ bhh1,
    const float* __restrict__ Wh1,  const float* __restrict__ bh1,
    const float* __restrict__ Wh2,  const float* __restrict__ bh2)
{
    __shared__ __align__(16) float h0b[2][HH];   // double-buffered states
    __shared__ __align__(16) float h1b[2][HH];
    __shared__ __align__(16) float sring[8][G3]; // xg ring (3 KB)
    __shared__ float shid[HU];

    const int p = blockIdx.x;
    const int t = threadIdx.x;
    const int e = g_pair_e[p];
    const bool lay0 = (t < 64);

    ull wR[8], wZ[8], wN[8];       // layer-0 half-rows / layer-1 merged+N
    ull wRa[4], wZa[4];            // layer-1 extra (input-gate quarters)
    ull bR = 0, bZ = 0, bNa = 0, bNg = 0;
    const float* xgp = g_xg + (size_t)p * LSEQ * G3;

    int j, sel;
    if (lay0) {
        j = t >> 1; sel = t & 1;               // half
        const ull* w0 = (const ull*)(Whh0 + (size_t)(e * G3 + j) * HH) + sel * 8;
        const ull* w1 = (const ull*)(Whh0 + (size_t)(e * G3 + j + 32) * HH) + sel * 8;
        const ull* w2 = (const ull*)(Whh0 + (size_t)(e * G3 + j + 64) * HH) + sel * 8;
#pragma unroll
        for (int i = 0; i < 8; ++i) { wR[i] = w0[i]; wZ[i] = w1[i]; wN[i] = w2[i]; }
        if (!sel) {
            bR = pk(bhh0[e * G3 + j], 0.f);
            bZ = pk(bhh0[e * G3 + j + 32], 0.f);
            bNg = pk(bhh0[e * G3 + j + 64], 0.f);
        }
    } else {
        int u = t - 64; j = u >> 2; sel = u & 3;   // quarter
        const ull* ia0 = (const ull*)(Wih1 + (size_t)(e * G3 + j) * HH) + sel * 4;
        const ull* ia1 = (const ull*)(Wih1 + (size_t)(e * G3 + j + 32) * HH) + sel * 4;
        const ull* ia2 = (const ull*)(Wih1 + (size_t)(e * G3 + j + 64) * HH) + sel * 4;
        const ull* ig0 = (const ull*)(Whh1 + (size_t)(e * G3 + j) * HH) + sel * 4;
        const ull* ig1 = (const ull*)(Whh1 + (size_t)(e * G3 + j + 32) * HH) + sel * 4;
        const ull* ig2 = (const ull*)(Whh1 + (size_t)(e * G3 + j + 64) * HH) + sel * 4;
#pragma unroll
        for (int i = 0; i < 4; ++i) {
            wRa[i] = ia0[i]; wR[i] = ig0[i];       // row r: input / recurrent
            wZa[i] = ia1[i]; wZ[i] = ig1[i];       // row z
            wN[i]  = ia2[i]; wN[4 + i] = ig2[i];   // row n: a in wN[0..3], g in wN[4..7]
        }
        if (!sel) {
            bR  = pk(bih1[e * G3 + j] + bhh1[e * G3 + j], 0.f);
            bZ  = pk(bih1[e * G3 + j + 32] + bhh1[e * G3 + j + 32], 0.f);
            bNa = pk(bih1[e * G3 + j + 64], 0.f);
            bNg = pk(bhh1[e * G3 + j + 64], 0.f);
        }
    }

    // init states + preload xg ring steps 0..3
    if (t < 64)  ((float*)h0b)[t] = 0.f;
    else if (t < 128) ((float*)h1b)[t - 64] = 0.f;
    for (int i = t; i < 4 * G3; i += 192)
        ((float*)sring)[i] = __ldg(xgp + i);
    __syncthreads();

#pragma unroll 1
    for (int it = 0; it <= LSEQ; ++it) {
        const int rp = it & 1, wp = rp ^ 1;
        if (lay0) {
            if (sel) {                       // odd lane: prefetch xg step it+4
                const int s = it + 4;
                if (s < LSEQ) {
                    const float* src = xgp + (size_t)s * G3 + j;
                    float v0 = __ldg(src), v1 = __ldg(src + 32), v2 = __ldg(src + 64);
                    float* dr = sring[s & 7] + j;
                    dr[0] = v0; dr[32] = v1; dr[64] = v2;
                }
            }
            if (it < LSEQ) {
                const ull* H = (const ull*)h0b[rp] + sel * 8;
                ull aR = bR, aZ = bZ, aN = bNg;
#pragma unroll
                for (int i = 0; i < 8; ++i) {
                    ull hv = H[i];
                    fma2(aR, wR[i], hv);
                    fma2(aZ, wZ[i], hv);
                    fma2(aN, wN[i], hv);
                }
                float2 u;
                u = upk(aR); float fR = u.x + u.y;
                u = upk(aZ); float fZ = u.x + u.y;
                u = upk(aN); float fN = u.x + u.y;
                fR += __shfl_xor_sync(0xffffffffu, fR, 1);
                fZ += __shfl_xor_sync(0xffffffffu, fZ, 1);
                fN += __shfl_xor_sync(0xffffffffu, fN, 1);
                if (!sel) {
                    const float* xr = sring[it & 7];
                    float r = sigm_fast(xr[j] + fR);
                    float z = sigm_fast(xr[j + 32] + fZ);
                    float n = tanh_fast(xr[j + 64] + r * fN);
                    h0b[wp][j] = (1.f - z) * n + z * h0b[rp][j];
                }
            }
        } else {
            if (it >= 1) {
                const ull* H0 = (const ull*)h0b[rp] + sel * 4;
                const ull* H1 = (const ull*)h1b[rp] + sel * 4;
                ull aR = bR, aZ = bZ, aNa = bNa, aNg = bNg;
#pragma unroll
                for (int i = 0; i < 4; ++i) {
                    ull h0v = H0[i], h1v = H1[i];
                    fma2(aR,  wRa[i], h0v);  fma2(aR,  wR[i],     h1v);
                    fma2(aZ,  wZa[i], h0v);  fma2(aZ,  wZ[i],     h1v);
                    fma2(aNa, wN[i],  h0v);  fma2(aNg, wN[4 + i], h1v);
                }
                float2 u;
                u = upk(aR);  float fR  = u.x + u.y;
                u = upk(aZ);  float fZ  = u.x + u.y;
                u = upk(aNa); float fNa = u.x + u.y;
                u = upk(aNg); float fNg = u.x + u.y;
                fR  += __shfl_xor_sync(0xffffffffu, fR, 1);
                fR  += __shfl_xor_sync(0xffffffffu, fR, 2);
                fZ  += __shfl_xor_sync(0xffffffffu, fZ, 1);
                fZ  += __shfl_xor_sync(0xffffffffu, fZ, 2);
                fNa += __shfl_xor_sync(0xffffffffu, fNa, 1);
                fNa += __shfl_xor_sync(0xffffffffu, fNa, 2);
                fNg += __shfl_xor_sync(0xffffffffu, fNg, 1);
                fNg += __shfl_xor_sync(0xffffffffu, fNg, 2);
                if (!sel) {
                    float r = sigm_fast(fR);
                    float z = sigm_fast(fZ);
                    float n = tanh_fast(fNa + r * fNg);
                    h1b[wp][j] = (1.f - z) * n + z * h1b[rp][j];
                }
            }
        }
        __syncthreads();
    }

    // final h1 is in h1b[(LSEQ+1)&1] = h1b[1]
    if (t < HU) {
        float acc = bh1[e * HU + t];
        const float* wr = Wh1 + (size_t)(e * HU + t) * HH;
#pragma unroll
        for (int k = 0; k < HH; ++k) acc = fmaf(__ldg(wr + k), h1b[1][k], acc);
        shid[t] = fmaxf(acc, 0.f);
    }
    __syncthreads();
    if (t < 32) {
        float v = shid[t] * __ldg(Wh2 + e * HU + t);
#pragma unroll
        for (int o = 16; o; o >>= 1) v += __shfl_xor_sync(0xffffffffu, v, o);
        if (t == 0) g_pred[p] = v + __ldg(bh2 + e);
    }
}

// ---------------- finalize: deterministic weighted combine ----------------
__global__ void moe_finalize(float* __restrict__ out) {
    int b = threadIdx.x;
    out[b] = g_pair_w[2 * b] * g_pred[2 * b] +
             g_pair_w[2 * b + 1] * g_pred[2 * b + 1];
}

// --------------------------------------------------------------------------
extern "C" void kernel_launch(void* const* d_in, const int* in_sizes, int n_in,
                              void* d_out, int out_size) {
    (void)in_sizes; (void)n_in; (void)out_size;
    const float* x       = (const float*)d_in[0];
    const int*   horizon = (const int*)  d_in[1];
    const float* W_in    = (const float*)d_in[2];
    const float* b_in    = (const float*)d_in[3];
    const float* emb     = (const float*)d_in[4];
    const float* W_gate  = (const float*)d_in[5];
    const float* b_gate  = (const float*)d_in[6];
    const float* Wih0    = (const float*)d_in[7];
    const float* Whh0    = (const float*)d_in[8];
    const float* bih0    = (const float*)d_in[9];
    const float* bhh0    = (const float*)d_in[10];
    const float* Wih1    = (const float*)d_in[11];
    const float* Whh1    = (const float*)d_in[12];
    const float* bih1    = (const float*)d_in[13];
    const float* bhh1    = (const float*)d_in[14];
    const float* Wh1     = (const float*)d_in[15];
    const float* bh1     = (const float*)d_in[16];
    const float* Wh2     = (const float*)d_in[17];
    const float* bh2     = (const float*)d_in[18];
    float* out = (float*)d_out;

    prep_Wc<<<EE, G3>>>(Wih0, W_in);
    prep_route<<<1, BB>>>(horizon, emb, W_gate, b_gate);
    prep_c0<<<NP, G3>>>(horizon, b_in, emb, Wih0, bih0);
    {
        dim3 grid(LSEQ / LT, NP);
        xg_gemm<<<grid, 288>>>(x);
    }
    moe_gru_scan<<<NP, 192>>>(Whh0, bhh0, Wih1, Whh1, bih1, bhh1,
                              Wh1, bh1, Wh2, bh2);
    moe_finalize<<<1, BB>>>(out);
}

// round 8
// speedup vs baseline: 2.0540x; 2.0540x over previous
#include <cuda_runtime.h>
#include <math.h>

#define BB   256
#define LSEQ 1800
#define FF   50
#define EE   4
#define HH   32
#define DD   64
#define G3   96      // 3*H
#define HU   32
#define NP   (2 * BB)        // 512 routed pairs
#define LT   90              // L-steps per GEMM block (1800/90 = 20 chunks)

typedef unsigned long long ull;

// ---------------- device scratch (no runtime allocation allowed) ----------
__device__ float g_Wc[EE * G3 * FF];           // Wih0 @ W_in (per expert 96x50)
__device__ int   g_pair_e[NP];                  // routed expert per pair
__device__ float g_pair_w[NP];                  // softmax weight per pair
__device__ float g_pred[NP];                    // expert prediction per pair
__device__ float g_c0[NP * G3];                 // fused layer-0 input bias
__device__ float g_xg[(size_t)NP * LSEQ * G3];  // precomputed input gates

// ---------------- packed f32x2 helpers ------------------------------------
__device__ __forceinline__ ull pk(float lo, float hi) {
    ull r; asm("mov.b64 %0, {%1, %2};" : "=l"(r) : "f"(lo), "f"(hi)); return r;
}
__device__ __forceinline__ float2 upk(ull v) {
    float2 r; asm("mov.b64 {%0, %1}, %2;" : "=f"(r.x), "=f"(r.y) : "l"(v)); return r;
}
__device__ __forceinline__ void fma2(ull& d, ull a, ull b) {
    asm("fma.rn.f32x2 %0, %1, %2, %3;" : "=l"(d) : "l"(a), "l"(b), "l"(d));
}

__device__ __forceinline__ float sigm_fast(float x) {
    return __fdividef(1.f, 1.f + __expf(-x));
}
__device__ __forceinline__ float tanh_fast(float x) {
    float e = __expf(2.f * x);
    return 1.f - __fdividef(2.f, e + 1.f);
}

// ---------------- prep: combined input weights Wc = Wih0 @ W_in -----------
__global__ void prep_Wc(const float* __restrict__ Wih0,
                        const float* __restrict__ W_in) {
    int e = blockIdx.x, j = threadIdx.x;
    float wr[DD];
    const float* src = Wih0 + (size_t)(e * G3 + j) * DD;
#pragma unroll
    for (int d = 0; d < DD; ++d) wr[d] = src[d];
    float* dst = g_Wc + (size_t)(e * G3 + j) * FF;
    for (int f = 0; f < FF; ++f) {
        float s = 0.f;
#pragma unroll
        for (int d = 0; d < DD; ++d) s = fmaf(wr[d], __ldg(W_in + d * FF + f), s);
        dst[f] = s;
    }
}

// ---------------- prep: gating (top-2 of 4, softmax over top-2) -----------
__global__ void prep_route(const int* __restrict__ horizon,
                           const float* __restrict__ emb,
                           const float* __restrict__ W_gate,
                           const float* __restrict__ b_gate) {
    int b = threadIdx.x;
    int hb = horizon[b];
    const float* he = emb + (size_t)hb * DD;
    float lg[EE];
#pragma unroll
    for (int e = 0; e < EE; ++e) {
        float s = b_gate[e];
        const float* w = W_gate + e * DD;
#pragma unroll
        for (int d = 0; d < DD; ++d) s = fmaf(w[d], he[d], s);
        lg[e] = s;
    }
    int m1 = 0;
#pragma unroll
    for (int e = 1; e < EE; ++e) if (lg[e] > lg[m1]) m1 = e;
    int m2 = -1;
#pragma unroll
    for (int e = 0; e < EE; ++e) {
        if (e == m1) continue;
        if (m2 < 0 || lg[e] > lg[m2]) m2 = e;
    }
    float e2  = expf(lg[m2] - lg[m1]);
    float inv = 1.f / (1.f + e2);
    g_pair_e[2 * b]     = m1;
    g_pair_e[2 * b + 1] = m2;
    g_pair_w[2 * b]     = inv;
    g_pair_w[2 * b + 1] = e2 * inv;
}

// ---------------- prep: c0(p,j) = bih0 + Wih0_row . (b_in + emb[horizon]) -
__global__ void prep_c0(const int* __restrict__ horizon,
                        const float* __restrict__ b_in,
                        const float* __restrict__ emb,
                        const float* __restrict__ Wih0,
                        const float* __restrict__ bih0) {
    int p = blockIdx.x, j = threadIdx.x;
    int b = p >> 1, e = g_pair_e[p];
    int hb = horizon[b];
    float c0 = bih0[e * G3 + j];
    const float* wi = Wih0 + (size_t)(e * G3 + j) * DD;
    const float* hv = emb + (size_t)hb * DD;
#pragma unroll
    for (int d = 0; d < DD; ++d) c0 = fmaf(wi[d], b_in[d] + hv[d], c0);
    g_c0[p * G3 + j] = c0;
}

// ---------------- xg GEMM: g_xg[p][l][j] = Wc[e][j].x[b][l] + c0(p,j) -----
__global__ void __launch_bounds__(288) xg_gemm(const float* __restrict__ x) {
    __shared__ __align__(16) float sx[LT * FF];

    const int p   = blockIdx.y;
    const int b   = p >> 1;
    const int e   = g_pair_e[p];
    const int t   = threadIdx.x;
    const int j   = t % G3;
    const int sub = t / G3;
    const int l0  = blockIdx.x * LT;

    const float* xsrc = x + (size_t)b * LSEQ * FF + (size_t)l0 * FF;
    for (int i = t; i < LT * FF; i += 288) sx[i] = __ldg(xsrc + i);

    ull wt[FF / 2];
    const ull* wc = (const ull*)(g_Wc + (size_t)(e * G3 + j) * FF);
#pragma unroll
    for (int i = 0; i < FF / 2; ++i) wt[i] = wc[i];
    const float c0 = __ldg(g_c0 + p * G3 + j);

    __syncthreads();

    float* dst = g_xg + ((size_t)p * LSEQ + l0) * G3 + j;
#pragma unroll 1
    for (int l = sub * (LT / 3); l < (sub + 1) * (LT / 3); ++l) {
        const ull* xr = (const ull*)(sx + l * FF);
        ull acc = pk(c0, 0.f);
#pragma unroll
        for (int i = 0; i < FF / 2; ++i) fma2(acc, wt[i], xr[i]);
        float2 u = upk(acc);
        dst[(size_t)l * G3] = u.x + u.y;
    }
}

// ---------------- main: 2-warp fused 2-layer GRU scan ---------------------
// 512 blocks x 64 threads, occ 4 (single wave, 59K regs/SM).
//   warp 0 lane j: layer-0 rows {j, j+32, j+64} FULL dots (step t)
//   warp 1 lane j: layer-1 rows {j, j+32, j+64} FULL dots (step t-1)
// No cross-lane reductions; h state double-buffered in smem; 1 barrier/step.
__global__ void __launch_bounds__(64, 4) moe_gru_scan(
    const float* __restrict__ Whh0, const float* __restrict__ bhh0,
    const float* __restrict__ Wih1, const float* __restrict__ Whh1,
    const float* __restrict__ bih1, const float* __restrict__ bhh1,
    const float* __restrict__ Wh1,  const float* __restrict__ bh1,
    const float* __restrict__ Wh2,  const float* __restrict__ bh2)
{
    __shared__ __align__(16) float h0x[2][HH];
    __shared__ __align__(16) float h1x[2][HH];

    const int p = blockIdx.x;
    const int t = threadIdx.x;
    const int e = g_pair_e[p];
    const int j = t & 31;
    const bool l0w = (t < 32);

    // Unified packed weight array (layer-0 uses [0..47], layer-1 all 96)
    ull W[96];
    float bR = 0.f, bZ = 0.f, bNa = 0.f, bNg = 0.f;

    if (l0w) {
        const ull* w0 = (const ull*)(Whh0 + (size_t)(e * G3 + j) * HH);
        const ull* w1 = (const ull*)(Whh0 + (size_t)(e * G3 + j + 32) * HH);
        const ull* w2 = (const ull*)(Whh0 + (size_t)(e * G3 + j + 64) * HH);
#pragma unroll
        for (int i = 0; i < 16; ++i) { W[i] = w0[i]; W[16 + i] = w1[i]; W[32 + i] = w2[i]; }
        bR  = bhh0[e * G3 + j];
        bZ  = bhh0[e * G3 + j + 32];
        bNg = bhh0[e * G3 + j + 64];
    } else {
        const ull* a0 = (const ull*)(Wih1 + (size_t)(e * G3 + j) * HH);
        const ull* a1 = (const ull*)(Wih1 + (size_t)(e * G3 + j + 32) * HH);
        const ull* a2 = (const ull*)(Wih1 + (size_t)(e * G3 + j + 64) * HH);
        const ull* g0 = (const ull*)(Whh1 + (size_t)(e * G3 + j) * HH);
        const ull* g1 = (const ull*)(Whh1 + (size_t)(e * G3 + j + 32) * HH);
        const ull* g2 = (const ull*)(Whh1 + (size_t)(e * G3 + j + 64) * HH);
#pragma unroll
        for (int i = 0; i < 16; ++i) {
            W[i]      = a0[i]; W[16 + i] = a1[i]; W[32 + i] = a2[i];
            W[48 + i] = g0[i]; W[64 + i] = g1[i]; W[80 + i] = g2[i];
        }
        bR  = bih1[e * G3 + j]      + bhh1[e * G3 + j];
        bZ  = bih1[e * G3 + j + 32] + bhh1[e * G3 + j + 32];
        bNa = bih1[e * G3 + j + 64];
        bNg = bhh1[e * G3 + j + 64];
    }

    // zero both buffers of both states
    ((float*)h0x)[t] = 0.f;
    ((float*)h1x)[t] = 0.f;

    // xg prefetch pipeline (distance 3), layer-0 warp only
    const float* xgp = g_xg + (size_t)p * LSEQ * G3 + j;
    float xc0 = 0, xc1 = 0, xc2 = 0, xa0 = 0, xa1 = 0, xa2 = 0,
          xb0 = 0, xb1 = 0, xb2 = 0;
    if (l0w) {
        xc0 = __ldg(xgp);            xc1 = __ldg(xgp + 32);            xc2 = __ldg(xgp + 64);
        xa0 = __ldg(xgp + G3);       xa1 = __ldg(xgp + G3 + 32);       xa2 = __ldg(xgp + G3 + 64);
        xb0 = __ldg(xgp + 2 * G3);   xb1 = __ldg(xgp + 2 * G3 + 32);   xb2 = __ldg(xgp + 2 * G3 + 64);
    }
    float hval = 0.f;                // own h element (h0[j] or h1[j])
    __syncthreads();

#pragma unroll 1
    for (int it = 0; it <= LSEQ; ++it) {
        const int rp = it & 1, wp = rp ^ 1;
        if (l0w) {
            float nf0 = 0, nf1 = 0, nf2 = 0;
            if (it + 3 < LSEQ) {
                const float* s = xgp + (size_t)(it + 3) * G3;
                nf0 = __ldg(s); nf1 = __ldg(s + 32); nf2 = __ldg(s + 64);
            }
            if (it < LSEQ) {
                const ull* H = (const ull*)h0x[rp];
                ull aR = 0, aZ = 0, aN = 0;
#pragma unroll
                for (int i = 0; i < 16; ++i) {
                    ull h = H[i];
                    fma2(aR, W[i], h);
                    fma2(aZ, W[16 + i], h);
                    fma2(aN, W[32 + i], h);
                }
                float2 u;
                u = upk(aR); float fR = u.x + u.y + bR;
                u = upk(aZ); float fZ = u.x + u.y + bZ;
                u = upk(aN); float fN = u.x + u.y + bNg;
                float r = sigm_fast(xc0 + fR);
                float z = sigm_fast(xc1 + fZ);
                float n = tanh_fast(xc2 + r * fN);
                hval = (1.f - z) * n + z * hval;
                h0x[wp][j] = hval;
            }
            xc0 = xa0; xc1 = xa1; xc2 = xa2;
            xa0 = xb0; xa1 = xb1; xa2 = xb2;
            xb0 = nf0; xb1 = nf1; xb2 = nf2;
        } else {
            if (it >= 1) {
                const ull* H0 = (const ull*)h0x[rp];
                const ull* H1 = (const ull*)h1x[rp];
                ull aR = 0, aZ = 0, aN = 0, gR = 0, gZ = 0, gN = 0;
#pragma unroll
                for (int i = 0; i < 16; ++i) {
                    ull u0 = H0[i], u1 = H1[i];
                    fma2(aR, W[i], u0);      fma2(gR, W[48 + i], u1);
                    fma2(aZ, W[16 + i], u0); fma2(gZ, W[64 + i], u1);
                    fma2(aN, W[32 + i], u0); fma2(gN, W[80 + i], u1);
                }
                float2 u;
                u = upk(aR); float fR = u.x + u.y;
                u = upk(gR); fR += u.x + u.y + bR;
                u = upk(aZ); float fZ = u.x + u.y;
                u = upk(gZ); fZ += u.x + u.y + bZ;
                u = upk(aN); float fNa = u.x + u.y + bNa;
                u = upk(gN); float fNg = u.x + u.y + bNg;
                float r = sigm_fast(fR);
                float z = sigm_fast(fZ);
                float n = tanh_fast(fNa + r * fNg);
                hval = (1.f - z) * n + z * hval;
                h1x[wp][j] = hval;
            }
        }
        __syncthreads();
    }

    // ---- head MLP on warp 0 (h1 final lives in h1x[1]) --------------------
    if (l0w) {
        float acc = bh1[e * HU + j];
        const float* wr = Wh1 + (size_t)(e * HU + j) * HH;
#pragma unroll
        for (int k = 0; k < HH; ++k) acc = fmaf(__ldg(wr + k), h1x[1][k], acc);
        float v = fmaxf(acc, 0.f) * __ldg(Wh2 + e * HU + j);
#pragma unroll
        for (int o = 16; o; o >>= 1) v += __shfl_xor_sync(0xffffffffu, v, o);
        if (j == 0) g_pred[p] = v + __ldg(bh2 + e);
    }
}

// ---------------- finalize: deterministic weighted combine ----------------
__global__ void moe_finalize(float* __restrict__ out) {
    int b = threadIdx.x;
    out[b] = g_pair_w[2 * b] * g_pred[2 * b] +
             g_pair_w[2 * b + 1] * g_pred[2 * b + 1];
}

// --------------------------------------------------------------------------
extern "C" void kernel_launch(void* const* d_in, const int* in_sizes, int n_in,
                              void* d_out, int out_size) {
    (void)in_sizes; (void)n_in; (void)out_size;
    const float* x       = (const float*)d_in[0];
    const int*   horizon = (const int*)  d_in[1];
    const float* W_in    = (const float*)d_in[2];
    const float* b_in    = (const float*)d_in[3];
    const float* emb     = (const float*)d_in[4];
    const float* W_gate  = (const float*)d_in[5];
    const float* b_gate  = (const float*)d_in[6];
    const float* Wih0    = (const float*)d_in[7];
    const float* Whh0    = (const float*)d_in[8];
    const float* bih0    = (const float*)d_in[9];
    const float* bhh0    = (const float*)d_in[10];
    const float* Wih1    = (const float*)d_in[11];
    const float* Whh1    = (const float*)d_in[12];
    const float* bih1    = (const float*)d_in[13];
    const float* bhh1    = (const float*)d_in[14];
    const float* Wh1     = (const float*)d_in[15];
    const float* bh1     = (const float*)d_in[16];
    const float* Wh2     = (const float*)d_in[17];
    const float* bh2     = (const float*)d_in[18];
    float* out = (float*)d_out;

    prep_Wc<<<EE, G3>>>(Wih0, W_in);
    prep_route<<<1, BB>>>(horizon, emb, W_gate, b_gate);
    prep_c0<<<NP, G3>>>(horizon, b_in, emb, Wih0, bih0);
    {
        dim3 grid(LSEQ / LT, NP);
        xg_gemm<<<grid, 288>>>(x);
    }
    moe_gru_scan<<<NP, 64>>>(Whh0, bhh0, Wih1, Whh1, bih1, bhh1,
                             Wh1, bh1, Wh2, bh2);
    moe_finalize<<<1, BB>>>(out);
}

// round 10
// speedup vs baseline: 2.3611x; 1.1495x over previous
#include <cuda_runtime.h>
#include <math.h>

#define BB   256
#define LSEQ 1800
#define FF   50
#define EE   4
#define HH   32
#define DD   64
#define G3   96      // 3*H
#define HU   32
#define NP   (2 * BB)        // 512 routed pairs
#define LT   90              // L-steps per GEMM block (1800/90 = 20 chunks)

typedef unsigned long long ull;

// ---------------- device scratch (no runtime allocation allowed) ----------
__device__ float g_Wc[EE * G3 * FF];           // Wih0 @ W_in (per expert 96x50)
__device__ int   g_pair_e[NP];                  // routed expert per pair
__device__ float g_pair_w[NP];                  // softmax weight per pair
__device__ float g_pred[NP];                    // expert prediction per pair
__device__ float g_c0[NP * G3];                 // fused layer-0 input bias
__device__ float g_xg[(size_t)NP * LSEQ * G3];  // precomputed input gates

// ---------------- packed f32x2 helpers ------------------------------------
__device__ __forceinline__ ull pk(float lo, float hi) {
    ull r; asm("mov.b64 %0, {%1, %2};" : "=l"(r) : "f"(lo), "f"(hi)); return r;
}
__device__ __forceinline__ float2 upk(ull v) {
    float2 r; asm("mov.b64 {%0, %1}, %2;" : "=f"(r.x), "=f"(r.y) : "l"(v)); return r;
}
__device__ __forceinline__ void fma2(ull& d, ull a, ull b) {
    asm("fma.rn.f32x2 %0, %1, %2, %3;" : "=l"(d) : "l"(a), "l"(b), "l"(d));
}

__device__ __forceinline__ float sigm_fast(float x) {
    return __fdividef(1.f, 1.f + __expf(-x));
}
__device__ __forceinline__ float tanh_fast(float x) {
    float e = __expf(2.f * x);
    return 1.f - __fdividef(2.f, e + 1.f);
}

// ---------------- prep: combined input weights Wc = Wih0 @ W_in -----------
__global__ void prep_Wc(const float* __restrict__ Wih0,
                        const float* __restrict__ W_in) {
    int e = blockIdx.x, j = threadIdx.x;
    float wr[DD];
    const float* src = Wih0 + (size_t)(e * G3 + j) * DD;
#pragma unroll
    for (int d = 0; d < DD; ++d) wr[d] = src[d];
    float* dst = g_Wc + (size_t)(e * G3 + j) * FF;
    for (int f = 0; f < FF; ++f) {
        float s = 0.f;
#pragma unroll
        for (int d = 0; d < DD; ++d) s = fmaf(wr[d], __ldg(W_in + d * FF + f), s);
        dst[f] = s;
    }
}

// ---------------- prep: gating (top-2 of 4, softmax over top-2) -----------
__global__ void prep_route(const int* __restrict__ horizon,
                           const float* __restrict__ emb,
                           const float* __restrict__ W_gate,
                           const float* __restrict__ b_gate) {
    int b = threadIdx.x;
    int hb = horizon[b];
    const float* he = emb + (size_t)hb * DD;
    float lg[EE];
#pragma unroll
    for (int e = 0; e < EE; ++e) {
        float s = b_gate[e];
        const float* w = W_gate + e * DD;
#pragma unroll
        for (int d = 0; d < DD; ++d) s = fmaf(w[d], he[d], s);
        lg[e] = s;
    }
    int m1 = 0;
#pragma unroll
    for (int e = 1; e < EE; ++e) if (lg[e] > lg[m1]) m1 = e;
    int m2 = -1;
#pragma unroll
    for (int e = 0; e < EE; ++e) {
        if (e == m1) continue;
        if (m2 < 0 || lg[e] > lg[m2]) m2 = e;
    }
    float e2  = expf(lg[m2] - lg[m1]);
    float inv = 1.f / (1.f + e2);
    g_pair_e[2 * b]     = m1;
    g_pair_e[2 * b + 1] = m2;
    g_pair_w[2 * b]     = inv;
    g_pair_w[2 * b + 1] = e2 * inv;
}

// ---------------- prep: c0(p,j) = bih0 + Wih0_row . (b_in + emb[horizon]) -
__global__ void prep_c0(const int* __restrict__ horizon,
                        const float* __restrict__ b_in,
                        const float* __restrict__ emb,
                        const float* __restrict__ Wih0,
                        const float* __restrict__ bih0) {
    int p = blockIdx.x, j = threadIdx.x;
    int b = p >> 1, e = g_pair_e[p];
    int hb = horizon[b];
    float c0 = bih0[e * G3 + j];
    const float* wi = Wih0 + (size_t)(e * G3 + j) * DD;
    const float* hv = emb + (size_t)hb * DD;
#pragma unroll
    for (int d = 0; d < DD; ++d) c0 = fmaf(wi[d], b_in[d] + hv[d], c0);
    g_c0[p * G3 + j] = c0;
}

// ---------------- xg GEMM: g_xg[p][l][j] = Wc[e][j].x[b][l] + c0(p,j) -----
__global__ void __launch_bounds__(288) xg_gemm(const float* __restrict__ x) {
    __shared__ __align__(16) float sx[LT * FF];

    const int p   = blockIdx.y;
    const int b   = p >> 1;
    const int e   = g_pair_e[p];
    const int t   = threadIdx.x;
    const int j   = t % G3;
    const int sub = t / G3;
    const int l0  = blockIdx.x * LT;

    const float* xsrc = x + (size_t)b * LSEQ * FF + (size_t)l0 * FF;
    for (int i = t; i < LT * FF; i += 288) sx[i] = __ldg(xsrc + i);

    ull wt[FF / 2];
    const ull* wc = (const ull*)(g_Wc + (size_t)(e * G3 + j) * FF);
#pragma unroll
    for (int i = 0; i < FF / 2; ++i) wt[i] = wc[i];
    const float c0 = __ldg(g_c0 + p * G3 + j);

    __syncthreads();

    float* dst = g_xg + ((size_t)p * LSEQ + l0) * G3 + j;
#pragma unroll 1
    for (int l = sub * (LT / 3); l < (sub + 1) * (LT / 3); ++l) {
        const ull* xr = (const ull*)(sx + l * FF);
        ull acc = pk(c0, 0.f);
#pragma unroll
        for (int i = 0; i < FF / 2; ++i) fma2(acc, wt[i], xr[i]);
        float2 u = upk(acc);
        dst[(size_t)l * G3] = u.x + u.y;
    }
}

// ---------------- main: 3-warp 3-stage fused 2-layer GRU scan -------------
// 512 blocks x 96 threads, occ 4 (single wave).
//   warp0 lane j: layer-0 rows {j,j+32,j+64} full dots, step t  (48 fma2)
//   warp1 lane j: layer-1 INPUT partials I[t-1] = Wih1 . h0[t-1] (48 fma2)
//   warp2 lane j: layer-1 RECURRENT G[t-2] = Whh1 . h1[t-3], combine with
//                 I[t-2], nonlinearity, h1 update               (48 fma2)
// One barrier per iteration; all handoffs cross the barrier; zero shfl.
__global__ void __launch_bounds__(96, 4) moe_gru_scan(
    const float* __restrict__ Whh0, const float* __restrict__ bhh0,
    const float* __restrict__ Wih1, const float* __restrict__ Whh1,
    const float* __restrict__ bih1, const float* __restrict__ bhh1,
    const float* __restrict__ Wh1,  const float* __restrict__ bh1,
    const float* __restrict__ Wh2,  const float* __restrict__ bh2)
{
    __shared__ __align__(16) float h0x[2][HH];   // h0 double buffer
    __shared__ __align__(16) float sI[2][G3];    // layer-1 input partials
    __shared__ __align__(16) float sh1[HH];      // h1 (warp2-private)

    const int p = blockIdx.x;
    const int t = threadIdx.x;
    const int e = g_pair_e[p];
    const int w = t >> 5;
    const int j = t & 31;

    // 48 packed weights per thread (96 regs) -> always register-resident
    ull W[48];
    float b0 = 0.f, b1 = 0.f, b2 = 0.f;

    if (w == 0) {
        const ull* w0 = (const ull*)(Whh0 + (size_t)(e * G3 + j) * HH);
        const ull* w1 = (const ull*)(Whh0 + (size_t)(e * G3 + j + 32) * HH);
        const ull* w2 = (const ull*)(Whh0 + (size_t)(e * G3 + j + 64) * HH);
#pragma unroll
        for (int i = 0; i < 16; ++i) { W[i] = w0[i]; W[16 + i] = w1[i]; W[32 + i] = w2[i]; }
        b0 = bhh0[e * G3 + j];            // recurrent biases (r,z,n)
        b1 = bhh0[e * G3 + j + 32];
        b2 = bhh0[e * G3 + j + 64];
    } else if (w == 1) {
        const ull* a0 = (const ull*)(Wih1 + (size_t)(e * G3 + j) * HH);
        const ull* a1 = (const ull*)(Wih1 + (size_t)(e * G3 + j + 32) * HH);
        const ull* a2 = (const ull*)(Wih1 + (size_t)(e * G3 + j + 64) * HH);
#pragma unroll
        for (int i = 0; i < 16; ++i) { W[i] = a0[i]; W[16 + i] = a1[i]; W[32 + i] = a2[i]; }
        b0 = bih1[e * G3 + j]      + bhh1[e * G3 + j];        // r: both biases
        b1 = bih1[e * G3 + j + 32] + bhh1[e * G3 + j + 32];   // z: both biases
        b2 = bih1[e * G3 + j + 64];                           // n: input bias only
    } else {
        const ull* g0 = (const ull*)(Whh1 + (size_t)(e * G3 + j) * HH);
        const ull* g1 = (const ull*)(Whh1 + (size_t)(e * G3 + j + 32) * HH);
        const ull* g2 = (const ull*)(Whh1 + (size_t)(e * G3 + j + 64) * HH);
#pragma unroll
        for (int i = 0; i < 16; ++i) { W[i] = g0[i]; W[16 + i] = g1[i]; W[32 + i] = g2[i]; }
        b2 = bhh1[e * G3 + j + 64];                           // n: recurrent bias
    }

    // init shared state
    if (t < 2 * HH) ((float*)h0x)[t] = 0.f;
    if (w == 2) sh1[j] = 0.f;

    // xg prefetch pipeline (distance 3), warp0 only
    const float* xgp = g_xg + (size_t)p * LSEQ * G3 + j;
    float xc0 = 0, xc1 = 0, xc2 = 0, xa0 = 0, xa1 = 0, xa2 = 0,
          xb0 = 0, xb1 = 0, xb2 = 0;
    if (w == 0) {
        xc0 = __ldg(xgp);            xc1 = __ldg(xgp + 32);            xc2 = __ldg(xgp + 64);
        xa0 = __ldg(xgp + G3);       xa1 = __ldg(xgp + G3 + 32);       xa2 = __ldg(xgp + G3 + 64);
        xb0 = __ldg(xgp + 2 * G3);   xb1 = __ldg(xgp + 2 * G3 + 32);   xb2 = __ldg(xgp + 2 * G3 + 64);
    }
    float hval = 0.f;                 // warp0: h0[j]; warp2: h1[j]
    __syncthreads();

#pragma unroll 1
    for (int it = 0; it <= LSEQ + 1; ++it) {
        const int rp = it & 1, wp = rp ^ 1;
        if (w == 0) {
            float nf0 = 0, nf1 = 0, nf2 = 0;
            if (it + 3 < LSEQ) {
                const float* s = xgp + (size_t)(it + 3) * G3;
                nf0 = __ldg(s); nf1 = __ldg(s + 32); nf2 = __ldg(s + 64);
            }
            if (it < LSEQ) {
                const ull* H = (const ull*)h0x[rp];
                ull aR = pk(b0, 0.f), aZ = pk(b1, 0.f), aN = pk(b2, 0.f);
#pragma unroll
                for (int i = 0; i < 16; ++i) {
                    ull h = H[i];
                    fma2(aR, W[i], h);
                    fma2(aZ, W[16 + i], h);
                    fma2(aN, W[32 + i], h);
                }
                float2 u;
                u = upk(aR); float fR = u.x + u.y;
                u = upk(aZ); float fZ = u.x + u.y;
                u = upk(aN); float fN = u.x + u.y;
                float r = sigm_fast(xc0 + fR);
                float z = sigm_fast(xc1 + fZ);
                float n = tanh_fast(xc2 + r * fN);
                hval = (1.f - z) * n + z * hval;
                h0x[wp][j] = hval;
            }
            xc0 = xa0; xc1 = xa1; xc2 = xa2;
            xa0 = xb0; xa1 = xb1; xa2 = xb2;
            xb0 = nf0; xb1 = nf1; xb2 = nf2;
        } else if (w == 1) {
            if (it >= 1 && it <= LSEQ) {          // I[it-1] from h0[it-1]
                const ull* H = (const ull*)h0x[rp];
                ull aR = pk(b0, 0.f), aZ = pk(b1, 0.f), aN = pk(b2, 0.f);
#pragma unroll
                for (int i = 0; i < 16; ++i) {
                    ull h = H[i];
                    fma2(aR, W[i], h);
                    fma2(aZ, W[16 + i], h);
                    fma2(aN, W[32 + i], h);
                }
                float2 u;
                u = upk(aR); sI[rp][j]      = u.x + u.y;
                u = upk(aZ); sI[rp][j + 32] = u.x + u.y;
                u = upk(aN); sI[rp][j + 64] = u.x + u.y;
            }
        } else {
            if (it >= 2) {                        // step s = it-2; I[s] in sI[wp]
                const ull* H = (const ull*)sh1;   // h1[s-1] (own previous write)
                ull gR = 0, gZ = 0, gN = pk(b2, 0.f);
#pragma unroll
                for (int i = 0; i < 16; ++i) {
                    ull h = H[i];
                    fma2(gR, W[i], h);
                    fma2(gZ, W[16 + i], h);
                    fma2(gN, W[32 + i], h);
                }
                float2 u;
                u = upk(gR); float fR = u.x + u.y + sI[wp][j];
                u = upk(gZ); float fZ = u.x + u.y + sI[wp][j + 32];
                u = upk(gN); float fN = u.x + u.y;
                float r = sigm_fast(fR);
                float z = sigm_fast(fZ);
                float n = tanh_fast(sI[wp][j + 64] + r * fN);
                hval = (1.f - z) * n + z * hval;
                sh1[j] = hval;
            }
        }
        __syncthreads();
    }

    // ---- head MLP on warp0 (final h1 in sh1) ------------------------------
    if (w == 0) {
        float acc = bh1[e * HU + j];
        const float* wr = Wh1 + (size_t)(e * HU + j) * HH;
#pragma unroll
        for (int k = 0; k < HH; ++k) acc = fmaf(__ldg(wr + k), sh1[k], acc);
        float v = fmaxf(acc, 0.f) * __ldg(Wh2 + e * HU + j);
#pragma unroll
        for (int o = 16; o; o >>= 1) v += __shfl_xor_sync(0xffffffffu, v, o);
        if (j == 0) g_pred[p] = v + __ldg(bh2 + e);
    }
}

// ---------------- finalize: deterministic weighted combine ----------------
__global__ void moe_finalize(float* __restrict__ out) {
    int b = threadIdx.x;
    out[b] = g_pair_w[2 * b] * g_pred[2 * b] +
             g_pair_w[2 * b + 1] * g_pred[2 * b + 1];
}

// --------------------------------------------------------------------------
extern "C" void kernel_launch(void* const* d_in, const int* in_sizes, int n_in,
                              void* d_out, int out_size) {
    (void)in_sizes; (void)n_in; (void)out_size;
    const float* x       = (const float*)d_in[0];
    const int*   horizon = (const int*)  d_in[1];
    const float* W_in    = (const float*)d_in[2];
    const float* b_in    = (const float*)d_in[3];
    const float* emb     = (const float*)d_in[4];
    const float* W_gate  = (const float*)d_in[5];
    const float* b_gate  = (const float*)d_in[6];
    const float* Wih0    = (const float*)d_in[7];
    const float* Whh0    = (const float*)d_in[8];
    const float* bih0    = (const float*)d_in[9];
    const float* bhh0    = (const float*)d_in[10];
    const float* Wih1    = (const float*)d_in[11];
    const float* Whh1    = (const float*)d_in[12];
    const float* bih1    = (const float*)d_in[13];
    const float* bhh1    = (const float*)d_in[14];
    const float* Wh1     = (const float*)d_in[15];
    const float* bh1     = (const float*)d_in[16];
    const float* Wh2     = (const float*)d_in[17];
    const float* bh2     = (const float*)d_in[18];
    float* out = (float*)d_out;

    prep_Wc<<<EE, G3>>>(Wih0, W_in);
    prep_route<<<1, BB>>>(horizon, emb, W_gate, b_gate);
    prep_c0<<<NP, G3>>>(horizon, b_in, emb, Wih0, bih0);
    {
        dim3 grid(LSEQ / LT, NP);
        xg_gemm<<<grid, 288>>>(x);
    }
    moe_gru_scan<<<NP, 96>>>(Whh0, bhh0, Wih1, Whh1, bih1, bhh1,
                             Wh1, bh1, Wh2, bh2);
    moe_finalize<<<1, BB>>>(out);
}

// round 11
// speedup vs baseline: 2.4077x; 1.0198x over previous
#include <cuda_runtime.h>
#include <math.h>

#define BB   256
#define LSEQ 1800
#define FF   50
#define EE   4
#define HH   32
#define DD   64
#define G3   96      // 3*H
#define HU   32
#define NP   (2 * BB)        // 512 routed pairs
#define LT   90              // L-steps per GEMM block (1800/90 = 20 chunks)

typedef unsigned long long ull;

// ---------------- device scratch (no runtime allocation allowed) ----------
__device__ float g_Wc[EE * G3 * FF];           // Wih0 @ W_in (per expert 96x50)
__device__ int   g_pair_e[NP];                  // routed expert per pair
__device__ float g_pair_w[NP];                  // softmax weight per pair
__device__ float g_pred[NP];                    // expert prediction per pair
__device__ float g_c0[NP * G3];                 // fused layer-0 input bias
__device__ float g_xg[(size_t)NP * LSEQ * G3];  // precomputed input gates

// ---------------- packed f32x2 helpers ------------------------------------
__device__ __forceinline__ ull pk(float lo, float hi) {
    ull r; asm("mov.b64 %0, {%1, %2};" : "=l"(r) : "f"(lo), "f"(hi)); return r;
}
__device__ __forceinline__ float2 upk(ull v) {
    float2 r; asm("mov.b64 {%0, %1}, %2;" : "=f"(r.x), "=f"(r.y) : "l"(v)); return r;
}
__device__ __forceinline__ void fma2(ull& d, ull a, ull b) {
    asm("fma.rn.f32x2 %0, %1, %2, %3;" : "=l"(d) : "l"(a), "l"(b), "l"(d));
}

__device__ __forceinline__ float sigm_fast(float x) {
    return __fdividef(1.f, 1.f + __expf(-x));
}
__device__ __forceinline__ float tanh_fast(float x) {
    float e = __expf(2.f * x);
    return 1.f - __fdividef(2.f, e + 1.f);
}

// ---------------- prep: combined input weights Wc = Wih0 @ W_in -----------
__global__ void prep_Wc(const float* __restrict__ Wih0,
                        const float* __restrict__ W_in) {
    int e = blockIdx.x, j = threadIdx.x;
    float wr[DD];
    const float* src = Wih0 + (size_t)(e * G3 + j) * DD;
#pragma unroll
    for (int d = 0; d < DD; ++d) wr[d] = src[d];
    float* dst = g_Wc + (size_t)(e * G3 + j) * FF;
    for (int f = 0; f < FF; ++f) {
        float s = 0.f;
#pragma unroll
        for (int d = 0; d < DD; ++d) s = fmaf(wr[d], __ldg(W_in + d * FF + f), s);
        dst[f] = s;
    }
}

// ---------------- prep: gating (top-2 of 4, softmax over top-2) -----------
__global__ void prep_route(const int* __restrict__ horizon,
                           const float* __restrict__ emb,
                           const float* __restrict__ W_gate,
                           const float* __restrict__ b_gate) {
    int b = threadIdx.x;
    int hb = horizon[b];
    const float* he = emb + (size_t)hb * DD;
    float lg[EE];
#pragma unroll
    for (int e = 0; e < EE; ++e) {
        float s = b_gate[e];
        const float* w = W_gate + e * DD;
#pragma unroll
        for (int d = 0; d < DD; ++d) s = fmaf(w[d], he[d], s);
        lg[e] = s;
    }
    int m1 = 0;
#pragma unroll
    for (int e = 1; e < EE; ++e) if (lg[e] > lg[m1]) m1 = e;
    int m2 = -1;
#pragma unroll
    for (int e = 0; e < EE; ++e) {
        if (e == m1) continue;
        if (m2 < 0 || lg[e] > lg[m2]) m2 = e;
    }
    float e2  = expf(lg[m2] - lg[m1]);
    float inv = 1.f / (1.f + e2);
    g_pair_e[2 * b]     = m1;
    g_pair_e[2 * b + 1] = m2;
    g_pair_w[2 * b]     = inv;
    g_pair_w[2 * b + 1] = e2 * inv;
}

// ---------------- prep: c0(p,j) = bih0 + Wih0_row . (b_in + emb[horizon]) -
__global__ void prep_c0(const int* __restrict__ horizon,
                        const float* __restrict__ b_in,
                        const float* __restrict__ emb,
                        const float* __restrict__ Wih0,
                        const float* __restrict__ bih0) {
    int p = blockIdx.x, j = threadIdx.x;
    int b = p >> 1, e = g_pair_e[p];
    int hb = horizon[b];
    float c0 = bih0[e * G3 + j];
    const float* wi = Wih0 + (size_t)(e * G3 + j) * DD;
    const float* hv = emb + (size_t)hb * DD;
#pragma unroll
    for (int d = 0; d < DD; ++d) c0 = fmaf(wi[d], b_in[d] + hv[d], c0);
    g_c0[p * G3 + j] = c0;
}

// ---------------- xg GEMM: g_xg[p][l][j] = Wc[e][j].x[b][l] + c0(p,j) -----
__global__ void __launch_bounds__(288) xg_gemm(const float* __restrict__ x) {
    __shared__ __align__(16) float sx[LT * FF];

    const int p   = blockIdx.y;
    const int b   = p >> 1;
    const int e   = g_pair_e[p];
    const int t   = threadIdx.x;
    const int j   = t % G3;
    const int sub = t / G3;
    const int l0  = blockIdx.x * LT;

    const float* xsrc = x + (size_t)b * LSEQ * FF + (size_t)l0 * FF;
    for (int i = t; i < LT * FF; i += 288) sx[i] = __ldg(xsrc + i);

    ull wt[FF / 2];
    const ull* wc = (const ull*)(g_Wc + (size_t)(e * G3 + j) * FF);
#pragma unroll
    for (int i = 0; i < FF / 2; ++i) wt[i] = wc[i];
    const float c0 = __ldg(g_c0 + p * G3 + j);

    __syncthreads();

    float* dst = g_xg + ((size_t)p * LSEQ + l0) * G3 + j;
#pragma unroll 1
    for (int l = sub * (LT / 3); l < (sub + 1) * (LT / 3); ++l) {
        const ull* xr = (const ull*)(sx + l * FF);
        ull acc = pk(c0, 0.f);
#pragma unroll
        for (int i = 0; i < FF / 2; ++i) fma2(acc, wt[i], xr[i]);
        float2 u = upk(acc);
        dst[(size_t)l * G3] = u.x + u.y;
    }
}

// ---------------- main: 4-warp role-rotated fused 2-layer GRU scan --------
// 512 blocks x 128 threads, occ 4 (single wave).
// role = (warp + (p>>2)) & 3 -> co-resident CTAs (p+148k) put DIFFERENT
// roles on each SMSP (148 = 37*4), balancing issue across sub-partitions.
//   role0 lane j: layer-0 rows {j,j+32,j+64} full dots, step t  (48 fma2)
//   role1 lane j: layer-1 INPUT partials I[t-1] = Wih1 . h0[t-1] (48 fma2)
//   role2 lane j: layer-1 RECURRENT + combine + h1 update, t-2   (48 fma2)
//   role3      : xg prefetch (LDG dist 6 -> reg pipe -> STS dist 4)
__global__ void __launch_bounds__(128, 4) moe_gru_scan(
    const float* __restrict__ Whh0, const float* __restrict__ bhh0,
    const float* __restrict__ Wih1, const float* __restrict__ Whh1,
    const float* __restrict__ bih1, const float* __restrict__ bhh1,
    const float* __restrict__ Wh1,  const float* __restrict__ bh1,
    const float* __restrict__ Wh2,  const float* __restrict__ bh2)
{
    __shared__ __align__(16) float h0x[2][HH];   // h0 double buffer
    __shared__ __align__(16) float sI[2][G3];    // layer-1 input partials
    __shared__ __align__(16) float sh1[HH];      // h1 (role2-private)
    __shared__ __align__(16) float sxr[8][G3];   // xg ring (3 KB)

    const int p = blockIdx.x;
    const int t = threadIdx.x;
    const int e = g_pair_e[p];
    const int w = t >> 5;
    const int j = t & 31;
    const int role = (w + (p >> 2)) & 3;

    // 48 packed weights per worker thread (96 regs) - register-resident
    ull W[48];
    float b0 = 0.f, b1 = 0.f, b2 = 0.f;

    if (role == 0) {
        const ull* w0 = (const ull*)(Whh0 + (size_t)(e * G3 + j) * HH);
        const ull* w1 = (const ull*)(Whh0 + (size_t)(e * G3 + j + 32) * HH);
        const ull* w2 = (const ull*)(Whh0 + (size_t)(e * G3 + j + 64) * HH);
#pragma unroll
        for (int i = 0; i < 16; ++i) { W[i] = w0[i]; W[16 + i] = w1[i]; W[32 + i] = w2[i]; }
        b0 = bhh0[e * G3 + j];
        b1 = bhh0[e * G3 + j + 32];
        b2 = bhh0[e * G3 + j + 64];
    } else if (role == 1) {
        const ull* a0 = (const ull*)(Wih1 + (size_t)(e * G3 + j) * HH);
        const ull* a1 = (const ull*)(Wih1 + (size_t)(e * G3 + j + 32) * HH);
        const ull* a2 = (const ull*)(Wih1 + (size_t)(e * G3 + j + 64) * HH);
#pragma unroll
        for (int i = 0; i < 16; ++i) { W[i] = a0[i]; W[16 + i] = a1[i]; W[32 + i] = a2[i]; }
        b0 = bih1[e * G3 + j]      + bhh1[e * G3 + j];
        b1 = bih1[e * G3 + j + 32] + bhh1[e * G3 + j + 32];
        b2 = bih1[e * G3 + j + 64];
    } else if (role == 2) {
        const ull* g0 = (const ull*)(Whh1 + (size_t)(e * G3 + j) * HH);
        const ull* g1 = (const ull*)(Whh1 + (size_t)(e * G3 + j + 32) * HH);
        const ull* g2 = (const ull*)(Whh1 + (size_t)(e * G3 + j + 64) * HH);
#pragma unroll
        for (int i = 0; i < 16; ++i) { W[i] = g0[i]; W[16 + i] = g1[i]; W[32 + i] = g2[i]; }
        b2 = bhh1[e * G3 + j + 64];
    }

    // init shared state (disjoint thread ranges)
    if (t < 32)       h0x[0][t] = 0.f;
    else if (t < 64)  h0x[1][t - 32] = 0.f;
    else if (t < 96)  sh1[t - 64] = 0.f;

    // preload xg ring steps 0..3 (cooperative, coalesced)
    const float* xgp = g_xg + (size_t)p * LSEQ * G3;
    for (int i = t; i < 4 * G3; i += 128) ((float*)sxr)[i] = __ldg(xgp + i);

    // role3 register pipe: steps 4 (A) and 5 (B)
    float rA0 = 0, rA1 = 0, rA2 = 0, rB0 = 0, rB1 = 0, rB2 = 0;
    if (role == 3) {
        const float* s4 = xgp + 4 * G3;
        const float* s5 = xgp + 5 * G3;
        rA0 = __ldg(s4 + j); rA1 = __ldg(s4 + j + 32); rA2 = __ldg(s4 + j + 64);
        rB0 = __ldg(s5 + j); rB1 = __ldg(s5 + j + 32); rB2 = __ldg(s5 + j + 64);
    }
    float hval = 0.f;                 // role0: h0[j]; role2: h1[j]
    __syncthreads();

#pragma unroll 1
    for (int it = 0; it <= LSEQ + 1; ++it) {
        const int rp = it & 1, wp = rp ^ 1;
        if (role == 0) {
            if (it < LSEQ) {
                const ulonglong2* H = (const ulonglong2*)h0x[rp];
                const float* xr = sxr[it & 7];
                ull aR = pk(b0, 0.f), aZ = pk(b1, 0.f), aN = pk(b2, 0.f);
#pragma unroll
                for (int i = 0; i < 8; ++i) {
                    ulonglong2 h = H[i];
                    fma2(aR, W[2 * i], h.x);     fma2(aR, W[2 * i + 1], h.y);
                    fma2(aZ, W[16 + 2 * i], h.x); fma2(aZ, W[17 + 2 * i], h.y);
                    fma2(aN, W[32 + 2 * i], h.x); fma2(aN, W[33 + 2 * i], h.y);
                }
                float2 u;
                u = upk(aR); float fR = u.x + u.y;
                u = upk(aZ); float fZ = u.x + u.y;
                u = upk(aN); float fN = u.x + u.y;
                float r = sigm_fast(xr[j] + fR);
                float z = sigm_fast(xr[j + 32] + fZ);
                float n = tanh_fast(xr[j + 64] + r * fN);
                hval = (1.f - z) * n + z * hval;
                h0x[wp][j] = hval;
            }
        } else if (role == 1) {
            if (it >= 1 && it <= LSEQ) {          // I[it-1] from h0[it-1]
                const ulonglong2* H = (const ulonglong2*)h0x[rp];
                ull aR = pk(b0, 0.f), aZ = pk(b1, 0.f), aN = pk(b2, 0.f);
#pragma unroll
                for (int i = 0; i < 8; ++i) {
                    ulonglong2 h = H[i];
                    fma2(aR, W[2 * i], h.x);      fma2(aR, W[2 * i + 1], h.y);
                    fma2(aZ, W[16 + 2 * i], h.x); fma2(aZ, W[17 + 2 * i], h.y);
                    fma2(aN, W[32 + 2 * i], h.x); fma2(aN, W[33 + 2 * i], h.y);
                }
                float2 u;
                u = upk(aR); sI[rp][j]      = u.x + u.y;
                u = upk(aZ); sI[rp][j + 32] = u.x + u.y;
                u = upk(aN); sI[rp][j + 64] = u.x + u.y;
            }
        } else if (role == 2) {
            if (it >= 2) {                        // step s = it-2; I[s] in sI[wp]
                const ulonglong2* H = (const ulonglong2*)sh1;
                ull gR = 0, gZ = 0, gN = pk(b2, 0.f);
#pragma unroll
                for (int i = 0; i < 8; ++i) {
                    ulonglong2 h = H[i];
                    fma2(gR, W[2 * i], h.x);      fma2(gR, W[2 * i + 1], h.y);
                    fma2(gZ, W[16 + 2 * i], h.x); fma2(gZ, W[17 + 2 * i], h.y);
                    fma2(gN, W[32 + 2 * i], h.x); fma2(gN, W[33 + 2 * i], h.y);
                }
                float2 u;
                u = upk(gR); float fR = u.x + u.y + sI[wp][j];
                u = upk(gZ); float fZ = u.x + u.y + sI[wp][j + 32];
                u = upk(gN); float fN = u.x + u.y;
                float r = sigm_fast(fR);
                float z = sigm_fast(fZ);
                float n = tanh_fast(sI[wp][j + 64] + r * fN);
                hval = (1.f - z) * n + z * hval;
                sh1[j] = hval;
            }
        } else {
            // role3: STS step it+4 (loaded 2 iters ago), LDG step it+6
            int s = it + 4;
            if (s < LSEQ) {
                float* d = sxr[s & 7];
                d[j] = rA0; d[j + 32] = rA1; d[j + 64] = rA2;
            }
            rA0 = rB0; rA1 = rB1; rA2 = rB2;
            int s2 = it + 6;
            if (s2 < LSEQ) {
                const float* src = xgp + (size_t)s2 * G3;
                rB0 = __ldg(src + j); rB1 = __ldg(src + j + 32); rB2 = __ldg(src + j + 64);
            }
        }
        __syncthreads();
    }

    // ---- head MLP on the role-0 warp (final h1 in sh1) --------------------
    if (role == 0) {
        float acc = bh1[e * HU + j];
        const float* wr = Wh1 + (size_t)(e * HU + j) * HH;
#pragma unroll
        for (int k = 0; k < HH; ++k) acc = fmaf(__ldg(wr + k), sh1[k], acc);
        float v = fmaxf(acc, 0.f) * __ldg(Wh2 + e * HU + j);
#pragma unroll
        for (int o = 16; o; o >>= 1) v += __shfl_xor_sync(0xffffffffu, v, o);
        if (j == 0) g_pred[p] = v + __ldg(bh2 + e);
    }
}

// ---------------- finalize: deterministic weighted combine ----------------
__global__ void moe_finalize(float* __restrict__ out) {
    int b = threadIdx.x;
    out[b] = g_pair_w[2 * b] * g_pred[2 * b] +
             g_pair_w[2 * b + 1] * g_pred[2 * b + 1];
}

// --------------------------------------------------------------------------
extern "C" void kernel_launch(void* const* d_in, const int* in_sizes, int n_in,
                              void* d_out, int out_size) {
    (void)in_sizes; (void)n_in; (void)out_size;
    const float* x       = (const float*)d_in[0];
    const int*   horizon = (const int*)  d_in[1];
    const float* W_in    = (const float*)d_in[2];
    const float* b_in    = (const float*)d_in[3];
    const float* emb     = (const float*)d_in[4];
    const float* W_gate  = (const float*)d_in[5];
    const float* b_gate  = (const float*)d_in[6];
    const float* Wih0    = (const float*)d_in[7];
    const float* Whh0    = (const float*)d_in[8];
    const float* bih0    = (const float*)d_in[9];
    const float* bhh0    = (const float*)d_in[10];
    const float* Wih1    = (const float*)d_in[11];
    const float* Whh1    = (const float*)d_in[12];
    const float* bih1    = (const float*)d_in[13];
    const float* bhh1    = (const float*)d_in[14];
    const float* Wh1     = (const float*)d_in[15];
    const float* bh1     = (const float*)d_in[16];
    const float* Wh2     = (const float*)d_in[17];
    const float* bh2     = (const float*)d_in[18];
    float* out = (float*)d_out;

    prep_Wc<<<EE, G3>>>(Wih0, W_in);
    prep_route<<<1, BB>>>(horizon, emb, W_gate, b_gate);
    prep_c0<<<NP, G3>>>(horizon, b_in, emb, Wih0, bih0);
    {
        dim3 grid(LSEQ / LT, NP);
        xg_gemm<<<grid, 288>>>(x);
    }
    moe_gru_scan<<<NP, 128>>>(Whh0, bhh0, Wih1, Whh1, bih1, bhh1,
                              Wh1, bh1, Wh2, bh2);
    moe_finalize<<<1, BB>>>(out);
}

// round 12
// speedup vs baseline: 2.8426x; 1.1806x over previous
#include <cuda_runtime.h>
#include <math.h>

#define BB   256
#define LSEQ 1800
#define FF   50
#define EE   4
#define HH   32
#define DD   64
#define G3   96      // 3*H
#define HU   32
#define NP   (2 * BB)        // 512 routed pairs
#define LT   90              // L-steps per GEMM block (1800/90 = 20 chunks)
#define CH   8               // scan chunk size (steps per phase)
#define NCH  (LSEQ / CH)     // 225 chunks

typedef unsigned long long ull;

// ---------------- device scratch (no runtime allocation allowed) ----------
__device__ float g_Wc[EE * G3 * FF];           // Wih0 @ W_in (per expert 96x50)
__device__ int   g_pair_e[NP];                  // routed expert per pair
__device__ float g_pair_w[NP];                  // softmax weight per pair
__device__ float g_pred[NP];                    // expert prediction per pair
__device__ float g_c0[NP * G3];                 // fused layer-0 input bias
__device__ float g_xg[(size_t)NP * LSEQ * G3];  // precomputed input gates

// ---------------- packed f32x2 helpers ------------------------------------
__device__ __forceinline__ ull pk(float lo, float hi) {
    ull r; asm("mov.b64 %0, {%1, %2};" : "=l"(r) : "f"(lo), "f"(hi)); return r;
}
__device__ __forceinline__ float2 upk(ull v) {
    float2 r; asm("mov.b64 {%0, %1}, %2;" : "=f"(r.x), "=f"(r.y) : "l"(v)); return r;
}
__device__ __forceinline__ void fma2(ull& d, ull a, ull b) {
    asm("fma.rn.f32x2 %0, %1, %2, %3;" : "=l"(d) : "l"(a), "l"(b), "l"(d));
}

__device__ __forceinline__ float sigm_fast(float x) {
    return __fdividef(1.f, 1.f + __expf(-x));
}
__device__ __forceinline__ float tanh_fast(float x) {
    float e = __expf(2.f * x);
    return 1.f - __fdividef(2.f, e + 1.f);
}

// ---------------- prep: combined input weights Wc = Wih0 @ W_in -----------
__global__ void prep_Wc(const float* __restrict__ Wih0,
                        const float* __restrict__ W_in) {
    int e = blockIdx.x, j = threadIdx.x;
    float wr[DD];
    const float* src = Wih0 + (size_t)(e * G3 + j) * DD;
#pragma unroll
    for (int d = 0; d < DD; ++d) wr[d] = src[d];
    float* dst = g_Wc + (size_t)(e * G3 + j) * FF;
    for (int f = 0; f < FF; ++f) {
        float s = 0.f;
#pragma unroll
        for (int d = 0; d < DD; ++d) s = fmaf(wr[d], __ldg(W_in + d * FF + f), s);
        dst[f] = s;
    }
}

// ---------------- prep: gating (top-2 of 4, softmax over top-2) -----------
__global__ void prep_route(const int* __restrict__ horizon,
                           const float* __restrict__ emb,
                           const float* __restrict__ W_gate,
                           const float* __restrict__ b_gate) {
    int b = threadIdx.x;
    int hb = horizon[b];
    const float* he = emb + (size_t)hb * DD;
    float lg[EE];
#pragma unroll
    for (int e = 0; e < EE; ++e) {
        float s = b_gate[e];
        const float* w = W_gate + e * DD;
#pragma unroll
        for (int d = 0; d < DD; ++d) s = fmaf(w[d], he[d], s);
        lg[e] = s;
    }
    int m1 = 0;
#pragma unroll
    for (int e = 1; e < EE; ++e) if (lg[e] > lg[m1]) m1 = e;
    int m2 = -1;
#pragma unroll
    for (int e = 0; e < EE; ++e) {
        if (e == m1) continue;
        if (m2 < 0 || lg[e] > lg[m2]) m2 = e;
    }
    float e2  = expf(lg[m2] - lg[m1]);
    float inv = 1.f / (1.f + e2);
    g_pair_e[2 * b]     = m1;
    g_pair_e[2 * b + 1] = m2;
    g_pair_w[2 * b]     = inv;
    g_pair_w[2 * b + 1] = e2 * inv;
}

// ---------------- prep: c0(p,j) = bih0 + Wih0_row . (b_in + emb[horizon]) -
__global__ void prep_c0(const int* __restrict__ horizon,
                        const float* __restrict__ b_in,
                        const float* __restrict__ emb,
                        const float* __restrict__ Wih0,
                        const float* __restrict__ bih0) {
    int p = blockIdx.x, j = threadIdx.x;
    int b = p >> 1, e = g_pair_e[p];
    int hb = horizon[b];
    float c0 = bih0[e * G3 + j];
    const float* wi = Wih0 + (size_t)(e * G3 + j) * DD;
    const float* hv = emb + (size_t)hb * DD;
#pragma unroll
    for (int d = 0; d < DD; ++d) c0 = fmaf(wi[d], b_in[d] + hv[d], c0);
    g_c0[p * G3 + j] = c0;
}

// ---------------- xg GEMM: g_xg[p][l][j] = Wc[e][j].x[b][l] + c0(p,j) -----
__global__ void __launch_bounds__(288) xg_gemm(const float* __restrict__ x) {
    __shared__ __align__(16) float sx[LT * FF];

    const int p   = blockIdx.y;
    const int b   = p >> 1;
    const int e   = g_pair_e[p];
    const int t   = threadIdx.x;
    const int j   = t % G3;
    const int sub = t / G3;
    const int l0  = blockIdx.x * LT;

    const float* xsrc = x + (size_t)b * LSEQ * FF + (size_t)l0 * FF;
    for (int i = t; i < LT * FF; i += 288) sx[i] = __ldg(xsrc + i);

    ull wt[FF / 2];
    const ull* wc = (const ull*)(g_Wc + (size_t)(e * G3 + j) * FF);
#pragma unroll
    for (int i = 0; i < FF / 2; ++i) wt[i] = wc[i];
    const float c0 = __ldg(g_c0 + p * G3 + j);

    __syncthreads();

    float* dst = g_xg + ((size_t)p * LSEQ + l0) * G3 + j;
#pragma unroll 1
    for (int l = sub * (LT / 3); l < (sub + 1) * (LT / 3); ++l) {
        const ull* xr = (const ull*)(sx + l * FF);
        ull acc = pk(c0, 0.f);
#pragma unroll
        for (int i = 0; i < FF / 2; ++i) fma2(acc, wt[i], xr[i]);
        float2 u = upk(acc);
        dst[(size_t)l * G3] = u.x + u.y;
    }
}

// ---------------- main: chunk-pipelined fused 2-layer GRU scan ------------
// 512 blocks x 128 threads, occ 4 (single wave). Block barrier only at
// CHUNK boundaries (227 phases); serial steps inside a chunk use
// warp-private STS/__syncwarp (producer warp == consumer warp).
//   role0: 8 serial layer-0 steps of chunk ph  -> h0 history buffer
//   role1: batched I = Wih1 . h0 for chunk ph-1 (no serial dependence)
//   role2: 8 serial layer-1 steps of chunk ph-2 (I partials + Whh1 . h1)
//   role3: prefetch xg chunk ph+1 (6x LDG.128 -> STS)
// role = (w + (p>>2)) & 3 balances roles across SMSPs for co-resident CTAs.
__global__ void __launch_bounds__(128, 4) moe_gru_scan(
    const float* __restrict__ Whh0, const float* __restrict__ bhh0,
    const float* __restrict__ Wih1, const float* __restrict__ Whh1,
    const float* __restrict__ bih1, const float* __restrict__ bhh1,
    const float* __restrict__ Wh1,  const float* __restrict__ bh1,
    const float* __restrict__ Wh2,  const float* __restrict__ bh2)
{
    __shared__ __align__(16) float h0h[2][CH][HH];   // h0 history (chunk parity)
    __shared__ __align__(16) float sI[2][CH][G3];    // layer-1 input partials
    __shared__ __align__(16) float sxg[2][CH][G3];   // xg chunks
    __shared__ __align__(16) float sh1[HH];          // h1 (role2-private)

    const int p = blockIdx.x;
    const int t = threadIdx.x;
    const int e = g_pair_e[p];
    const int w = t >> 5;
    const int j = t & 31;
    const int role = (w + (p >> 2)) & 3;

    // 48 packed weights per worker thread (96 regs) - register-resident
    ull W[48];
    float b0 = 0.f, b1 = 0.f, b2 = 0.f;

    if (role == 0) {
        const ull* w0 = (const ull*)(Whh0 + (size_t)(e * G3 + j) * HH);
        const ull* w1 = (const ull*)(Whh0 + (size_t)(e * G3 + j + 32) * HH);
        const ull* w2 = (const ull*)(Whh0 + (size_t)(e * G3 + j + 64) * HH);
#pragma unroll
        for (int i = 0; i < 16; ++i) { W[i] = w0[i]; W[16 + i] = w1[i]; W[32 + i] = w2[i]; }
        b0 = bhh0[e * G3 + j];
        b1 = bhh0[e * G3 + j + 32];
        b2 = bhh0[e * G3 + j + 64];
    } else if (role == 1) {
        const ull* a0 = (const ull*)(Wih1 + (size_t)(e * G3 + j) * HH);
        const ull* a1 = (const ull*)(Wih1 + (size_t)(e * G3 + j + 32) * HH);
        const ull* a2 = (const ull*)(Wih1 + (size_t)(e * G3 + j + 64) * HH);
#pragma unroll
        for (int i = 0; i < 16; ++i) { W[i] = a0[i]; W[16 + i] = a1[i]; W[32 + i] = a2[i]; }
        b0 = bih1[e * G3 + j]      + bhh1[e * G3 + j];
        b1 = bih1[e * G3 + j + 32] + bhh1[e * G3 + j + 32];
        b2 = bih1[e * G3 + j + 64];
    } else if (role == 2) {
        const ull* g0 = (const ull*)(Whh1 + (size_t)(e * G3 + j) * HH);
        const ull* g1 = (const ull*)(Whh1 + (size_t)(e * G3 + j + 32) * HH);
        const ull* g2 = (const ull*)(Whh1 + (size_t)(e * G3 + j + 64) * HH);
#pragma unroll
        for (int i = 0; i < 16; ++i) { W[i] = g0[i]; W[16 + i] = g1[i]; W[32 + i] = g2[i]; }
        b2 = bhh1[e * G3 + j + 64];
    }

    // init shared state: h "before chunk 0" lives at h0h[1][CH-1]; h1 = 0
    if (t < 32)      h0h[1][CH - 1][t] = 0.f;
    else if (t < 64) sh1[t - 32] = 0.f;

    // preload xg chunk 0 (cooperative, coalesced)
    const float* xgp = g_xg + (size_t)p * LSEQ * G3;
    for (int i = t; i < CH * G3; i += 128) ((float*)sxg[0])[i] = __ldg(xgp + i);

    float hval = 0.f;                 // role0: h0[j]; role2: h1[j]
    __syncthreads();

#pragma unroll 1
    for (int ph = 0; ph < NCH + 2; ++ph) {
        if (role == 0) {
            if (ph < NCH) {
                const int cb = ph & 1;
                const float* xc = (const float*)sxg[cb];
                const float* hp = h0h[cb ^ 1][CH - 1];
#pragma unroll 1
                for (int s = 0; s < CH; ++s) {
                    const ulonglong2* H = (const ulonglong2*)hp;
                    ull aR = pk(b0, 0.f), aZ = pk(b1, 0.f), aN = pk(b2, 0.f);
#pragma unroll
                    for (int i = 0; i < 8; ++i) {
                        ulonglong2 h = H[i];
                        fma2(aR, W[2 * i], h.x);      fma2(aR, W[2 * i + 1], h.y);
                        fma2(aZ, W[16 + 2 * i], h.x); fma2(aZ, W[17 + 2 * i], h.y);
                        fma2(aN, W[32 + 2 * i], h.x); fma2(aN, W[33 + 2 * i], h.y);
                    }
                    float2 u;
                    u = upk(aR); float fR = u.x + u.y;
                    u = upk(aZ); float fZ = u.x + u.y;
                    u = upk(aN); float fN = u.x + u.y;
                    const float* xr = xc + s * G3;
                    float r = sigm_fast(xr[j] + fR);
                    float z = sigm_fast(xr[j + 32] + fZ);
                    float n = tanh_fast(xr[j + 64] + r * fN);
                    hval = (1.f - z) * n + z * hval;
                    float* hw = h0h[cb][s];
                    hw[j] = hval;
                    __syncwarp();
                    hp = hw;
                }
            }
        } else if (role == 1) {
            if (ph >= 1 && ph <= NCH) {           // chunk c = ph-1 (batched)
                const int cb = (ph - 1) & 1;
#pragma unroll 1
                for (int s = 0; s < CH; ++s) {
                    const ulonglong2* H = (const ulonglong2*)h0h[cb][s];
                    ull aR = pk(b0, 0.f), aZ = pk(b1, 0.f), aN = pk(b2, 0.f);
#pragma unroll
                    for (int i = 0; i < 8; ++i) {
                        ulonglong2 h = H[i];
                        fma2(aR, W[2 * i], h.x);      fma2(aR, W[2 * i + 1], h.y);
                        fma2(aZ, W[16 + 2 * i], h.x); fma2(aZ, W[17 + 2 * i], h.y);
                        fma2(aN, W[32 + 2 * i], h.x); fma2(aN, W[33 + 2 * i], h.y);
                    }
                    float2 u;
                    float* d = sI[cb][s];
                    u = upk(aR); d[j]      = u.x + u.y;
                    u = upk(aZ); d[j + 32] = u.x + u.y;
                    u = upk(aN); d[j + 64] = u.x + u.y;
                }
            }
        } else if (role == 2) {
            if (ph >= 2) {                        // chunk c = ph-2 (serial)
                const int cb = ph & 1;            // (ph-2)&1 == ph&1
#pragma unroll 1
                for (int s = 0; s < CH; ++s) {
                    const ulonglong2* H = (const ulonglong2*)sh1;
                    ull gR = 0, gZ = 0, gN = pk(b2, 0.f);
#pragma unroll
                    for (int i = 0; i < 8; ++i) {
                        ulonglong2 h = H[i];
                        fma2(gR, W[2 * i], h.x);      fma2(gR, W[2 * i + 1], h.y);
                        fma2(gZ, W[16 + 2 * i], h.x); fma2(gZ, W[17 + 2 * i], h.y);
                        fma2(gN, W[32 + 2 * i], h.x); fma2(gN, W[33 + 2 * i], h.y);
                    }
                    const float* Ipart = sI[cb][s];
                    float2 u;
                    u = upk(gR); float fR = u.x + u.y + Ipart[j];
                    u = upk(gZ); float fZ = u.x + u.y + Ipart[j + 32];
                    u = upk(gN); float fN = u.x + u.y;
                    float r = sigm_fast(fR);
                    float z = sigm_fast(fZ);
                    float n = tanh_fast(Ipart[j + 64] + r * fN);
                    hval = (1.f - z) * n + z * hval;
                    sh1[j] = hval;
                    __syncwarp();
                }
            }
        } else {
            if (ph + 1 < NCH) {                   // prefetch xg chunk ph+1
                const float4* src = (const float4*)(xgp + (size_t)(ph + 1) * CH * G3);
                float4* dst = (float4*)sxg[(ph + 1) & 1];
#pragma unroll
                for (int k = 0; k < (CH * G3) / (4 * 32); ++k)
                    dst[j + 32 * k] = __ldg(src + j + 32 * k);
            }
        }
        __syncthreads();
    }

    // ---- head MLP on warp 0 (final h1 in sh1) -----------------------------
    if (w == 0) {
        float acc = bh1[e * HU + j];
        const float* wr = Wh1 + (size_t)(e * HU + j) * HH;
#pragma unroll
        for (int k = 0; k < HH; ++k) acc = fmaf(__ldg(wr + k), sh1[k], acc);
        float v = fmaxf(acc, 0.f) * __ldg(Wh2 + e * HU + j);
#pragma unroll
        for (int o = 16; o; o >>= 1) v += __shfl_xor_sync(0xffffffffu, v, o);
        if (j == 0) g_pred[p] = v + __ldg(bh2 + e);
    }
}

// ---------------- finalize: deterministic weighted combine ----------------
__global__ void moe_finalize(float* __restrict__ out) {
    int b = threadIdx.x;
    out[b] = g_pair_w[2 * b] * g_pred[2 * b] +
             g_pair_w[2 * b + 1] * g_pred[2 * b + 1];
}

// --------------------------------------------------------------------------
extern "C" void kernel_launch(void* const* d_in, const int* in_sizes, int n_in,
                              void* d_out, int out_size) {
    (void)in_sizes; (void)n_in; (void)out_size;
    const float* x       = (const float*)d_in[0];
    const int*   horizon = (const int*)  d_in[1];
    const float* W_in    = (const float*)d_in[2];
    const float* b_in    = (const float*)d_in[3];
    const float* emb     = (const float*)d_in[4];
    const float* W_gate  = (const float*)d_in[5];
    const float* b_gate  = (const float*)d_in[6];
    const float* Wih0    = (const float*)d_in[7];
    const float* Whh0    = (const float*)d_in[8];
    const float* bih0    = (const float*)d_in[9];
    const float* bhh0    = (const float*)d_in[10];
    const float* Wih1    = (const float*)d_in[11];
    const float* Whh1    = (const float*)d_in[12];
    const float* bih1    = (const float*)d_in[13];
    const float* bhh1    = (const float*)d_in[14];
    const float* Wh1     = (const float*)d_in[15];
    const float* bh1     = (const float*)d_in[16];
    const float* Wh2     = (const float*)d_in[17];
    const float* bh2     = (const float*)d_in[18];
    float* out = (float*)d_out;

    prep_Wc<<<EE, G3>>>(Wih0, W_in);
    prep_route<<<1, BB>>>(horizon, emb, W_gate, b_gate);
    prep_c0<<<NP, G3>>>(horizon, b_in, emb, Wih0, bih0);
    {
        dim3 grid(LSEQ / LT, NP);
        xg_gemm<<<grid, 288>>>(x);
    }
    moe_gru_scan<<<NP, 128>>>(Whh0, bhh0, Wih1, Whh1, bih1, bhh1,
                              Wh1, bh1, Wh2, bh2);
    moe_finalize<<<1, BB>>>(out);
}